// round 1
// baseline (speedup 1.0000x reference)
#include <cuda_runtime.h>
#include <math.h>

#define DIM   768
#define HEADS 16
#define DK    48
#define B     2
#define S     2048
#define MROWS (B * S)          // 4096

// Scratch (static device globals — no runtime allocation)
__device__ float g_q[B * HEADS * S * DK];
__device__ float g_k[B * HEADS * S * DK];
__device__ float g_v[B * HEADS * S * DK];
__device__ float g_ctx[MROWS * DIM];

// ---------------------------------------------------------------------------
// Tiled SGEMM: out = A[M,K] @ W[N,K]^T + bias[N]
// MODE 0: out is [M,N] row-major
// MODE 1: out scattered to [B, HEADS, S, DK]  (m -> (b,s), n -> (h,d))
// Tile: BM=BN=64, BK=16, 256 threads, 4x4 microtile.
// ---------------------------------------------------------------------------
template <int MODE>
__global__ __launch_bounds__(256)
void gemm_bias_kernel(const float* __restrict__ A,
                      const float* __restrict__ W,
                      const float* __restrict__ bias,
                      float* __restrict__ out,
                      int M, int N, int K)
{
    __shared__ float As[16][64];
    __shared__ float Bs[16][64];

    const int tid = threadIdx.x;
    const int bm  = blockIdx.y * 64;
    const int bn  = blockIdx.x * 64;
    const int ty  = tid >> 4;          // 0..15
    const int tx  = tid & 15;          // 0..15

    // load mapping: 64 rows x 4 float4 columns
    const int lr = tid >> 2;           // 0..63 row within tile
    const int lk = (tid & 3) * 4;      // 0,4,8,12 k-offset

    float c[4][4];
    #pragma unroll
    for (int i = 0; i < 4; i++)
        #pragma unroll
        for (int j = 0; j < 4; j++) c[i][j] = 0.0f;

    const float* Aptr = A + (size_t)(bm + lr) * K + lk;
    const float* Wptr = W + (size_t)(bn + lr) * K + lk;

    for (int k0 = 0; k0 < K; k0 += 16) {
        float4 av = *(const float4*)(Aptr + k0);
        float4 wv = *(const float4*)(Wptr + k0);
        As[lk + 0][lr] = av.x; As[lk + 1][lr] = av.y;
        As[lk + 2][lr] = av.z; As[lk + 3][lr] = av.w;
        Bs[lk + 0][lr] = wv.x; Bs[lk + 1][lr] = wv.y;
        Bs[lk + 2][lr] = wv.z; Bs[lk + 3][lr] = wv.w;
        __syncthreads();

        #pragma unroll
        for (int kk = 0; kk < 16; kk++) {
            float a[4], bb[4];
            #pragma unroll
            for (int i = 0; i < 4; i++) a[i]  = As[kk][ty * 4 + i];
            #pragma unroll
            for (int j = 0; j < 4; j++) bb[j] = Bs[kk][tx * 4 + j];
            #pragma unroll
            for (int i = 0; i < 4; i++)
                #pragma unroll
                for (int j = 0; j < 4; j++)
                    c[i][j] = fmaf(a[i], bb[j], c[i][j]);
        }
        __syncthreads();
    }

    #pragma unroll
    for (int i = 0; i < 4; i++) {
        const int m = bm + ty * 4 + i;
        #pragma unroll
        for (int j = 0; j < 4; j++) {
            const int n = bn + tx * 4 + j;
            const float v = c[i][j] + bias[n];
            if (MODE == 0) {
                out[(size_t)m * N + n] = v;
            } else {
                const int bidx = m / S;
                const int s    = m % S;
                const int h    = n / DK;
                const int d    = n % DK;
                out[(((size_t)bidx * HEADS + h) * S + s) * DK + d] = v;
            }
        }
    }
}

// ---------------------------------------------------------------------------
// Flash attention: one thread owns one query row.
// Block = 128 threads = 128 query rows. K/V staged 32 keys at a time in smem.
// Online softmax with rescale-on-new-max (no score array).
// Writes ctx in [B, S, DIM] layout (heads re-interleaved).
// ---------------------------------------------------------------------------
__global__ __launch_bounds__(128)
void attention_kernel(const float* __restrict__ Q,
                      const float* __restrict__ K,
                      const float* __restrict__ V,
                      float* __restrict__ ctx)
{
    const int qt = blockIdx.x;     // query tile: 0..15
    const int h  = blockIdx.y;     // head
    const int b  = blockIdx.z;     // batch
    const int t  = threadIdx.x;    // 0..127 -> query row within tile

    __shared__ float Ks[32 * DK];
    __shared__ float Vs[32 * DK];

    const size_t head_off = ((size_t)b * HEADS + h) * S * DK;
    const float scale = rsqrtf((float)DK);

    // q row into registers (pre-scaled)
    float qreg[DK];
    const float* qrow = Q + head_off + (size_t)(qt * 128 + t) * DK;
    #pragma unroll
    for (int d = 0; d < DK; d++) qreg[d] = qrow[d] * scale;

    float acc[DK];
    #pragma unroll
    for (int d = 0; d < DK; d++) acc[d] = 0.0f;
    float mrun = -INFINITY;
    float lrun = 0.0f;

    const float* kbase = K + head_off;
    const float* vbase = V + head_off;

    for (int kt = 0; kt < S; kt += 32) {
        // cooperative coalesced load of 32 keys + 32 values
        #pragma unroll
        for (int i = t; i < 32 * DK; i += 128) {
            Ks[i] = kbase[(size_t)kt * DK + i];
            Vs[i] = vbase[(size_t)kt * DK + i];
        }
        __syncthreads();

        #pragma unroll 4
        for (int j = 0; j < 32; j++) {
            float s = 0.0f;
            #pragma unroll
            for (int d = 0; d < DK; d++)
                s = fmaf(qreg[d], Ks[j * DK + d], s);

            if (s > mrun) {
                const float corr = __expf(mrun - s);  // exp(-inf)=0 on first key
                lrun *= corr;
                #pragma unroll
                for (int d = 0; d < DK; d++) acc[d] *= corr;
                mrun = s;
            }
            const float p = __expf(s - mrun);
            lrun += p;
            #pragma unroll
            for (int d = 0; d < DK; d++)
                acc[d] = fmaf(p, Vs[j * DK + d], acc[d]);
        }
        __syncthreads();
    }

    const float inv = 1.0f / lrun;
    float* orow = ctx + ((size_t)b * S + qt * 128 + t) * DIM + h * DK;
    #pragma unroll
    for (int d = 0; d < DK; d++) orow[d] = acc[d] * inv;
}

// ---------------------------------------------------------------------------
extern "C" void kernel_launch(void* const* d_in, const int* in_sizes, int n_in,
                              void* d_out, int out_size)
{
    const float* x  = (const float*)d_in[0];
    const float* Wq = (const float*)d_in[1];
    const float* bq = (const float*)d_in[2];
    const float* Wk = (const float*)d_in[3];
    const float* bk = (const float*)d_in[4];
    const float* Wv = (const float*)d_in[5];
    const float* bv = (const float*)d_in[6];
    const float* Wo = (const float*)d_in[7];
    const float* bo = (const float*)d_in[8];
    float* out = (float*)d_out;

    float *q, *k, *v, *ctx;
    cudaGetSymbolAddress((void**)&q,   g_q);
    cudaGetSymbolAddress((void**)&k,   g_k);
    cudaGetSymbolAddress((void**)&v,   g_v);
    cudaGetSymbolAddress((void**)&ctx, g_ctx);

    dim3 gblk(256);
    dim3 ggrd(DIM / 64, MROWS / 64);   // (12, 64)

    // Q/K/V projections with fused head-layout scatter
    gemm_bias_kernel<1><<<ggrd, gblk>>>(x, Wq, bq, q, MROWS, DIM, DIM);
    gemm_bias_kernel<1><<<ggrd, gblk>>>(x, Wk, bk, k, MROWS, DIM, DIM);
    gemm_bias_kernel<1><<<ggrd, gblk>>>(x, Wv, bv, v, MROWS, DIM, DIM);

    // Attention
    dim3 agrd(S / 128, HEADS, B);      // (16, 16, 2)
    attention_kernel<<<agrd, 128>>>(q, k, v, ctx);

    // Output projection
    gemm_bias_kernel<0><<<ggrd, gblk>>>(ctx, Wo, bo, out, MROWS, DIM, DIM);
}